// round 14
// baseline (speedup 1.0000x reference)
#include <cuda_runtime.h>
#include <cuda_fp16.h>
#include <cstdint>
#include <math.h>

// ---------------------------------------------------------------- constants
#define BSZ 2
#define NSEQ 4096
#define DMODEL 1024
#define NHEADS 8
#define DH 128
#define RRANK 4
#define KMAX 21
#define M_TOTAL (BSZ * NSEQ)   // 8192

// ---------------------------------------------------------------- scratch
__device__ __half g_x16[M_TOTAL * DMODEL];   // x fp16
__device__ __half g_phi[M_TOTAL * DMODEL];   // xproj hi
__device__ __half g_plo[M_TOTAL * DMODEL];   // xproj lo
__device__ __half g_wi16[DMODEL * DMODEL];   // W_in fp16
__device__ __half g_wo16[DMODEL * DMODEL];   // W_out fp16
__device__ __half g_c16[M_TOTAL * DMODEL];   // concat fp16

// ---------------------------------------------------------------- helpers (base-ISA only)
__device__ __forceinline__ uint32_t smem_u32(const void* p) {
    uint32_t a;
    asm("{ .reg .u64 t; cvta.to.shared.u64 t, %1; cvt.u32.u64 %0, t; }" : "=r"(a) : "l"(p));
    return a;
}
__device__ __forceinline__ void cp_async16(uint32_t dst, const void* src) {
    asm volatile("cp.async.cg.shared.global [%0], [%1], 16;" :: "r"(dst), "l"(src));
}
__device__ __forceinline__ void ldm4(uint32_t* r, uint32_t addr) {
    asm volatile("ldmatrix.sync.aligned.m8n8.x4.shared.b16 {%0,%1,%2,%3}, [%4];"
                 : "=r"(r[0]), "=r"(r[1]), "=r"(r[2]), "=r"(r[3]) : "r"(addr));
}
__device__ __forceinline__ void mma_f16(float* d, const uint32_t* a, uint32_t b0, uint32_t b1) {
    asm volatile(
        "mma.sync.aligned.m16n8k16.row.col.f32.f16.f16.f32 "
        "{%0,%1,%2,%3}, {%4,%5,%6,%7}, {%8,%9}, {%0,%1,%2,%3};"
        : "+f"(d[0]), "+f"(d[1]), "+f"(d[2]), "+f"(d[3])
        : "r"(a[0]), "r"(a[1]), "r"(a[2]), "r"(a[3]), "r"(b0), "r"(b1));
}

// ---------------------------------------------------------------- conversion
__global__ __launch_bounds__(256)
void round_f16(const float* __restrict__ s, __half* __restrict__ o, int n4)
{
    int i = blockIdx.x * blockDim.x + threadIdx.x;
    if (i >= n4) return;
    float4 v = ((const float4*)s)[i];
    ((half2*)o)[2 * i]     = half2(__float2half(v.x), __float2half(v.y));
    ((half2*)o)[2 * i + 1] = half2(__float2half(v.z), __float2half(v.w));
}

// ---------------------------------------------------------------- mma.sync GEMM: C = A @ B^T + bias (single-pass fp16)
// CTA 128x128, 4 warps @ 64x64, BK=32 (2 chunks of 16 per stage),
// 4-stage cp.async ring, 2 CTAs/SM.
#define BM 128
#define BN 128
#define NKT 32                 // 1024 / 32
#define PITCH 48               // bytes per smem row (16 f16 + 8 pad)
#define MATB (128 * PITCH)     // 6144 B per matrix per 16-col chunk
#define CHUNKB (2 * MATB)      // A+B chunk block = 12288 B
#define STAGEB (2 * CHUNKB)    // 2 chunks = 24576 B
#define SMEM_GEMM (4 * STAGEB) // 98304 B

template<int OUT_MODE>
__global__ __launch_bounds__(128, 2)
void gemm_mma(const __half* __restrict__ Af, const __half* __restrict__ Bf,
              const float* __restrict__ bias, float* __restrict__ C,
              __half* __restrict__ Ohi, __half* __restrict__ Olo)
{
    extern __shared__ char smem[];
    const uint32_t sb = smem_u32(smem);
    const int tid  = threadIdx.x;
    const int lane = tid & 31;
    const int wid  = tid >> 5;          // 0..3
    const int m0 = blockIdx.y * BM;
    const int n0 = blockIdx.x * BN;
    const int wm = (wid >> 1) * 64;     // warp m-offset
    const int wn = (wid & 1) * 64;      // warp n-offset

    const __half* srcs[2] = { Af + (size_t)m0 * DMODEL, Bf + (size_t)n0 * DMODEL };

    // load one 32-col stage (2 chunks of 16) = 8 x cp.async16 per thread
    auto load_stage = [&](int kt, int s) {
        const uint32_t base = sb + s * STAGEB;
#pragma unroll
        for (int ch = 0; ch < 2; ch++) {
            const int kcol = kt * 32 + ch * 16;
            const uint32_t cbase = base + ch * CHUNKB;
#pragma unroll
            for (int i = 0; i < 4; i++) {
                int g    = tid + i * 128;       // 0..511
                int mat  = g >> 8;              // 0..1
                int rem  = g & 255;
                int row  = rem >> 1;            // 0..127
                int half = rem & 1;
                const __half* src = srcs[mat] + (size_t)row * DMODEL + kcol + half * 8;
                cp_async16(cbase + mat * MATB + row * PITCH + half * 16, src);
            }
        }
        asm volatile("cp.async.commit_group;" ::: "memory");
    };

    const uint32_t a_row  = (lane & 15);
    const uint32_t a_koff = (lane >> 4) * 16;
    const uint32_t b_row  = (lane & 7) + ((lane >> 4) << 3);
    const uint32_t b_koff = ((lane >> 3) & 1) * 16;

    // fragments for both chunks of the current stage
    uint32_t fa[2][4][4], fb[2][4][4];
    auto load_frags = [&](int s, int ch) {
        const uint32_t stb = sb + s * STAGEB + ch * CHUNKB;
#pragma unroll
        for (int mi = 0; mi < 4; mi++)
            ldm4(fa[ch][mi], stb + (wm + mi * 16 + a_row) * PITCH + a_koff);
#pragma unroll
        for (int t = 0; t < 4; t++)
            ldm4(fb[ch][t], stb + MATB + (wn + t * 16 + b_row) * PITCH + b_koff);
    };

    float acc[4][8][4];
#pragma unroll
    for (int a = 0; a < 4; a++)
#pragma unroll
        for (int b = 0; b < 8; b++)
#pragma unroll
            for (int c = 0; c < 4; c++) acc[a][b][c] = 0.f;

    load_stage(0, 0);
    load_stage(1, 1);
    load_stage(2, 2);

    for (int kt = 0; kt < NKT; kt++) {
        // this thread: stage kt+1 copies complete; barrier makes it CTA-wide
        // and is the WAR fence before load_stage overwrites ring slot kt-1.
        asm volatile("cp.async.wait_group 1;" ::: "memory");
        __syncthreads();

        const int s = kt & 3;
        load_frags(s, 0);
        load_frags(s, 1);

#pragma unroll
        for (int ch = 0; ch < 2; ch++)
#pragma unroll
            for (int mi = 0; mi < 4; mi++)
#pragma unroll
                for (int ni = 0; ni < 8; ni++) {
                    const int t = ni >> 1, pp = (ni & 1) * 2;
                    mma_f16(acc[mi][ni], fa[ch][mi], fb[ch][t][pp], fb[ch][t][pp + 1]);
                }

        if (kt + 3 < NKT) load_stage(kt + 3, (kt + 3) & 3);
        else              asm volatile("cp.async.commit_group;" ::: "memory");
    }

    // epilogue
    const float* bs = bias + n0 + wn;
#pragma unroll
    for (int mi = 0; mi < 4; mi++) {
        int r0 = mi * 16 + (lane >> 2);
#pragma unroll
        for (int ni = 0; ni < 8; ni++) {
            int c = ni * 8 + (lane & 3) * 2;
            float b0 = bs[c], b1 = bs[c + 1];
            float v00 = acc[mi][ni][0] + b0, v01 = acc[mi][ni][1] + b1;
            float v10 = acc[mi][ni][2] + b0, v11 = acc[mi][ni][3] + b1;
            size_t off0 = (size_t)(m0 + wm + r0)     * DMODEL + n0 + wn + c;
            size_t off1 = (size_t)(m0 + wm + r0 + 8) * DMODEL + n0 + wn + c;
            if (OUT_MODE == 0) {
                *(float2*)&C[off0] = make_float2(v00, v01);
                *(float2*)&C[off1] = make_float2(v10, v11);
            } else {
                __half h00 = __float2half(v00), h01 = __float2half(v01);
                __half h10 = __float2half(v10), h11 = __float2half(v11);
                *(half2*)&Ohi[off0] = half2(h00, h01);
                *(half2*)&Ohi[off1] = half2(h10, h11);
                *(half2*)&Olo[off0] = half2(__float2half(v00 - __half2float(h00)),
                                            __float2half(v01 - __half2float(h01)));
                *(half2*)&Olo[off1] = half2(__float2half(v10 - __half2float(h10)),
                                            __float2half(v11 - __half2float(h11)));
            }
        }
    }
}

// ---------------------------------------------------------------- middle stage (fused over all heads)
#define TILE_N 32
#define MAXROWS (TILE_N + KMAX - 1)   // 52

template<int K>
__device__ __forceinline__ void dka_impl(int h, int b, int n0, int d,
    const float* __restrict__ Wc, const float* __restrict__ Aar,
    const float* __restrict__ Var, const float* __restrict__ basep,
    const float* __restrict__ alphas,
    float (*sh)[DH + 1], float* A_sh, float (*c_sh)[RRANK])
{
    constexpr int PAD  = K / 2;
    constexpr int ROWS = TILE_N + K - 1;

    const __half* xh = g_phi + (size_t)b * NSEQ * DMODEL + h * DH;
    const __half* xl = g_plo + (size_t)b * NSEQ * DMODEL + h * DH;
#pragma unroll
    for (int i = 0; i < ROWS; i++) {
        int n = n0 + i - PAD;
        float v = 0.f;
        if (n >= 0 && n < NSEQ) {
            size_t off = (size_t)n * DMODEL + d;
            v = __half2float(xh[off]) + __half2float(xl[off]);
        }
        sh[i][d] = v;
    }
    if (d < RRANK * K) {
        int r = d / K, j = d % K;
        A_sh[r * K + j] = Aar[(size_t)h * RRANK * KMAX + r * KMAX + j];
    }
    __syncthreads();

    {   // c[nl][r] = <window_center, Wc[:,r]>
        int nl = d >> 2, r = d & 3;
        const float* wc = Wc + (size_t)h * DH * RRANK + r;
        float s = 0.f;
#pragma unroll 8
        for (int dd = 0; dd < DH; dd++)
            s = fmaf(sh[nl + PAD][dd], wc[dd * RRANK], s);
        c_sh[nl][r] = s;
    }
    __syncthreads();

    const float alpha = 1.f / (1.f + expf(-alphas[h]));
    const float beta  = 1.f - alpha;

    float baser[K];
#pragma unroll
    for (int j = 0; j < K; j++)
        baser[j] = basep[((size_t)h * KMAX + j) * DH + d];
    float Vr[RRANK];
#pragma unroll
    for (int r = 0; r < RRANK; r++)
        Vr[r] = Var[((size_t)h * RRANK + r) * DH + d];

    __half* oc = g_c16 + (size_t)b * NSEQ * DMODEL + h * DH + d;

#pragma unroll 4
    for (int nl = 0; nl < TILE_N; nl++) {
        float tb = 0.f, s0 = 0.f, s1 = 0.f, s2 = 0.f, s3 = 0.f;
#pragma unroll
        for (int j = 0; j < K; j++) {
            float xv = sh[nl + j][d];
            tb = fmaf(baser[j],        xv, tb);
            s0 = fmaf(A_sh[0 * K + j], xv, s0);
            s1 = fmaf(A_sh[1 * K + j], xv, s1);
            s2 = fmaf(A_sh[2 * K + j], xv, s2);
            s3 = fmaf(A_sh[3 * K + j], xv, s3);
        }
        float dynsum = c_sh[nl][0] * Vr[0] * s0 + c_sh[nl][1] * Vr[1] * s1
                     + c_sh[nl][2] * Vr[2] * s2 + c_sh[nl][3] * Vr[3] * s3;
        float val = alpha * dynsum + beta * tb;
        oc[(size_t)(n0 + nl) * DMODEL] = __float2half(val);
    }
}

__global__ __launch_bounds__(128)
void dka_mid_fused(const float* __restrict__ Wc, const float* __restrict__ Aar,
                   const float* __restrict__ Var, const float* __restrict__ basep,
                   const float* __restrict__ alphas)
{
    __shared__ float sh[MAXROWS][DH + 1];
    __shared__ float A_sh[RRANK * KMAX];
    __shared__ float c_sh[TILE_N][RRANK];

    const int d  = threadIdx.x;
    const int h  = blockIdx.y;
    const int b  = blockIdx.z;
    const int n0 = blockIdx.x * TILE_N;

    switch (h >> 1) {
        case 0: dka_impl<3 >(h, b, n0, d, Wc, Aar, Var, basep, alphas, sh, A_sh, c_sh); break;
        case 1: dka_impl<7 >(h, b, n0, d, Wc, Aar, Var, basep, alphas, sh, A_sh, c_sh); break;
        case 2: dka_impl<11>(h, b, n0, d, Wc, Aar, Var, basep, alphas, sh, A_sh, c_sh); break;
        default: dka_impl<21>(h, b, n0, d, Wc, Aar, Var, basep, alphas, sh, A_sh, c_sh); break;
    }
}

// ---------------------------------------------------------------- launch
extern "C" void kernel_launch(void* const* d_in, const int* in_sizes, int n_in,
                              void* d_out, int out_size)
{
    const float* x      = (const float*)d_in[0];
    const float* W_in   = (const float*)d_in[1];
    const float* b_in   = (const float*)d_in[2];
    const float* W_out  = (const float*)d_in[3];
    const float* b_out  = (const float*)d_in[4];
    const float* Wc     = (const float*)d_in[5];
    const float* A      = (const float*)d_in[6];
    const float* V      = (const float*)d_in[7];
    const float* basep  = (const float*)d_in[8];
    const float* alphas = (const float*)d_in[9];
    float* out = (float*)d_out;

    __half *x16, *phi, *plo, *wi16, *wo16, *c16;
    cudaGetSymbolAddress((void**)&x16,  g_x16);
    cudaGetSymbolAddress((void**)&phi,  g_phi);  cudaGetSymbolAddress((void**)&plo,  g_plo);
    cudaGetSymbolAddress((void**)&wi16, g_wi16); cudaGetSymbolAddress((void**)&wo16, g_wo16);
    cudaGetSymbolAddress((void**)&c16,  g_c16);

    cudaFuncSetAttribute(gemm_mma<0>, cudaFuncAttributeMaxDynamicSharedMemorySize, SMEM_GEMM);
    cudaFuncSetAttribute(gemm_mma<1>, cudaFuncAttributeMaxDynamicSharedMemorySize, SMEM_GEMM);

    // 1. conversions
    int n4x = M_TOTAL * DMODEL / 4;
    round_f16<<<n4x / 256, 256>>>(x, x16, n4x);
    int n4w = DMODEL * DMODEL / 4;
    round_f16<<<n4w / 256, 256>>>(W_in,  wi16, n4w);
    round_f16<<<n4w / 256, 256>>>(W_out, wo16, n4w);

    dim3 ggrid(DMODEL / BN, M_TOTAL / BM);   // (8, 64)

    // 2. GEMM1: xproj(hi/lo) = x @ W_in^T + b_in
    gemm_mma<1><<<ggrid, 128, SMEM_GEMM>>>(x16, wi16, b_in, nullptr, phi, plo);

    // 3. middle stage (fused heads), writes concat as fp16
    dka_mid_fused<<<dim3(NSEQ / TILE_N, NHEADS, BSZ), 128>>>(Wc, A, V, basep, alphas);

    // 4. GEMM2: out = concat @ W_out^T + b_out
    gemm_mma<0><<<ggrid, 128, SMEM_GEMM>>>(c16, wo16, b_out, out, nullptr, nullptr);
}